// round 2
// baseline (speedup 1.0000x reference)
#include <cuda_runtime.h>

// Problem constants
#define N_B   128
#define N_W   64
#define L_W   32
#define T_D   108
#define P_D   19
#define F_D   128
#define M_D   128
#define NWALK 8192          // N_B * N_W
#define SCALE 0.08838834764831845f   // 1/sqrt(128)

// Scratch (device globals; no allocation allowed)
__device__ float g_emb[2 * NWALK * M_D];   // [sel][b][nw][c]  (8 MB)
__device__ float g_Wvl[F_D * M_D];         // Wv @ Wl folded
__device__ float g_bvl[M_D];               // 32*bv@Wl + bl

// ---------------------------------------------------------------------------
// Kernel 0: fold Wvl = Wv @ Wl ; bvl = 32*bv@Wl + bl   (split-K, 512 thr)
// ---------------------------------------------------------------------------
__global__ void prep_kernel(const float* __restrict__ Wv, const float* __restrict__ bv,
                            const float* __restrict__ Wl, const float* __restrict__ bl) {
    __shared__ float part[4][128];
    const int c = threadIdx.x & 127;
    const int s = threadIdx.x >> 7;           // 0..3 k-slice
    const int j0 = s * 32;
    float acc = 0.f;
    if (blockIdx.x < 128) {
        const int k = blockIdx.x;
#pragma unroll 8
        for (int j = 0; j < 32; ++j) acc += Wv[k * 128 + j0 + j] * Wl[(j0 + j) * 128 + c];
    } else {
#pragma unroll 8
        for (int j = 0; j < 32; ++j) acc += 32.0f * bv[j0 + j] * Wl[(j0 + j) * 128 + c];
    }
    part[s][c] = acc;
    __syncthreads();
    if (threadIdx.x < 128) {
        float r = part[0][c] + part[1][c] + part[2][c] + part[3][c];
        if (blockIdx.x < 128) g_Wvl[blockIdx.x * 128 + c] = r;
        else                  g_bvl[c] = r + bl[c];
    }
}

// ---------------------------------------------------------------------------
// Kernel 1: per-walk attention. One block per 2 walks (4096 blocks, 512 thr).
// Shared layout (floats):
//   xTp [128][72]  transposed pos-selected features, 2 walks (cols w*36+r)
//   xTd [19][72]   delta (neg-selected - pos-selected), first 19 feature rows
//   qS  [4][32][128]  q rows, pre-scaled  (ws = w*2+sel)
//   kT  [4][128][33]  k transposed, stride 33 (conflict-free)
//   sc  [4][32][32]   softmax probs
//   scol[128], yv[512]
// ---------------------------------------------------------------------------
#define K1_XTP   0
#define K1_XTD   (128 * 72)                  // 9216
#define K1_QS    (K1_XTD + P_D * 72)         // 10584
#define K1_KT    (K1_QS + 4 * 32 * 128)      // 26968
#define K1_SC    (K1_KT + 4 * 128 * 33)      // 43864
#define K1_SCOL  (K1_SC + 4 * 32 * 32)       // 47960
#define K1_YV    (K1_SCOL + 128)             // 48088
#define K1_SMEM  ((K1_YV + 512) * 4)         // 194400 bytes

__global__ void __launch_bounds__(512, 1)
walk_kernel(const float* __restrict__ timef, const float* __restrict__ posf,
            const float* __restrict__ negf, const float* __restrict__ wgt,
            const int* __restrict__ sgn,
            const float* __restrict__ Wq, const float* __restrict__ bq,
            const float* __restrict__ Wk, const float* __restrict__ bk) {
    extern __shared__ float sm[];
    float* xTp  = sm + K1_XTP;
    float* xTd  = sm + K1_XTD;
    float* qS   = sm + K1_QS;
    float* kT   = sm + K1_KT;
    float* sc   = sm + K1_SC;
    float* scol = sm + K1_SCOL;
    float* yv   = sm + K1_YV;

    const int tid = threadIdx.x;
    const int blk = blockIdx.x;          // handles walks 2*blk, 2*blk+1

    // -------- phase 0: load + transpose features (2 walks) --------
    for (int idx = tid; idx < 2 * L_W * T_D; idx += 512) {
        int w   = idx / (L_W * T_D);
        int rem = idx - w * (L_W * T_D);
        int r = rem / T_D, t = rem - r * T_D;
        xTp[(P_D + t) * 72 + w * 36 + r] =
            timef[(long)(2 * blk + w) * (L_W * T_D) + rem];
    }
    if (tid < 2 * L_W) {
        int w = tid >> 5, r = tid & 31;
        xTp[127 * 72 + w * 36 + r] = wgt[(2 * blk + w) * L_W + r];
    }
    for (int idx = tid; idx < 2 * L_W * P_D; idx += 512) {
        int w   = idx / (L_W * P_D);
        int rem = idx - w * (L_W * P_D);
        int r = rem / P_D, p = rem - r * P_D;
        long gb = (long)(2 * blk + w) * (L_W * P_D) + rem;
        float vp = posf[gb];
        float vn = negf[gb];
        bool ps = (sgn[(2 * blk + w) * L_W + r] > 0);
        float xp = ps ? vp : vn;
        float xn = ps ? vn : vp;
        xTp[p * 72 + w * 36 + r] = xp;
        xTd[p * 72 + w * 36 + r] = xn - xp;
    }
    __syncthreads();

    // -------- phase 1: Q,K projections (pos full pass, then 19-dim delta) --------
    {
        const int c  = tid & 127;
        const int r0 = (tid >> 7) * 8;       // 0,8,16,24
#pragma unroll
        for (int mat = 0; mat < 2; ++mat) {
            const float* W  = mat ? Wk : Wq;
            const float* bb = mat ? bk : bq;
            float accP[16];
#pragma unroll
            for (int i = 0; i < 16; ++i) accP[i] = 0.f;
#pragma unroll 4
            for (int kk = 0; kk < 128; ++kk) {
                float wv = W[kk * 128 + c];
                const float4 a0 = *(const float4*)&xTp[kk * 72 + r0];
                const float4 a1 = *(const float4*)&xTp[kk * 72 + r0 + 4];
                const float4 b0 = *(const float4*)&xTp[kk * 72 + 36 + r0];
                const float4 b1 = *(const float4*)&xTp[kk * 72 + 36 + r0 + 4];
                accP[0]  += a0.x * wv; accP[1]  += a0.y * wv;
                accP[2]  += a0.z * wv; accP[3]  += a0.w * wv;
                accP[4]  += a1.x * wv; accP[5]  += a1.y * wv;
                accP[6]  += a1.z * wv; accP[7]  += a1.w * wv;
                accP[8]  += b0.x * wv; accP[9]  += b0.y * wv;
                accP[10] += b0.z * wv; accP[11] += b0.w * wv;
                accP[12] += b1.x * wv; accP[13] += b1.y * wv;
                accP[14] += b1.z * wv; accP[15] += b1.w * wv;
            }
            float dac[16];
#pragma unroll
            for (int i = 0; i < 16; ++i) dac[i] = 0.f;
            for (int kk = 0; kk < P_D; ++kk) {
                float wv = W[kk * 128 + c];
                const float4 a0 = *(const float4*)&xTd[kk * 72 + r0];
                const float4 a1 = *(const float4*)&xTd[kk * 72 + r0 + 4];
                const float4 b0 = *(const float4*)&xTd[kk * 72 + 36 + r0];
                const float4 b1 = *(const float4*)&xTd[kk * 72 + 36 + r0 + 4];
                dac[0]  += a0.x * wv; dac[1]  += a0.y * wv;
                dac[2]  += a0.z * wv; dac[3]  += a0.w * wv;
                dac[4]  += a1.x * wv; dac[5]  += a1.y * wv;
                dac[6]  += a1.z * wv; dac[7]  += a1.w * wv;
                dac[8]  += b0.x * wv; dac[9]  += b0.y * wv;
                dac[10] += b0.z * wv; dac[11] += b0.w * wv;
                dac[12] += b1.x * wv; dac[13] += b1.y * wv;
                dac[14] += b1.z * wv; dac[15] += b1.w * wv;
            }
            const float bias = bb[c];
            if (mat == 0) {
#pragma unroll
                for (int i = 0; i < 8; ++i) {
                    int row = r0 + i;
                    qS[0 * 4096 + row * 128 + c] = (accP[i]      + bias) * SCALE;
                    qS[1 * 4096 + row * 128 + c] = (accP[i]      + dac[i]     + bias) * SCALE;
                    qS[2 * 4096 + row * 128 + c] = (accP[8 + i]  + bias) * SCALE;
                    qS[3 * 4096 + row * 128 + c] = (accP[8 + i]  + dac[8 + i] + bias) * SCALE;
                }
            } else {
#pragma unroll
                for (int i = 0; i < 8; ++i) {
                    int row = r0 + i;
                    kT[0 * 4224 + c * 33 + row] = accP[i]     + bias;
                    kT[1 * 4224 + c * 33 + row] = accP[i]     + dac[i]     + bias;
                    kT[2 * 4224 + c * 33 + row] = accP[8 + i] + bias;
                    kT[3 * 4224 + c * 33 + row] = accP[8 + i] + dac[8 + i] + bias;
                }
            }
        }
    }
    __syncthreads();

    // -------- phase 2: scores + softmax (warp per 8 rows of one ws) --------
    {
        const int lane = tid & 31;
        const int wid  = tid >> 5;          // 0..15
        const int ws   = wid >> 2;          // 0..3 = w*2+sel
        const int rb   = (wid & 3) * 8;     // 8 rows per warp
        const float* qbase = &qS[ws * 4096 + rb * 128];
        const float* kb    = &kT[ws * 4224 + lane];
        float acc[8];
#pragma unroll
        for (int i = 0; i < 8; ++i) acc[i] = 0.f;
#pragma unroll 4
        for (int c4 = 0; c4 < 32; ++c4) {
            float k0 = kb[(4 * c4 + 0) * 33];
            float k1 = kb[(4 * c4 + 1) * 33];
            float k2 = kb[(4 * c4 + 2) * 33];
            float k3 = kb[(4 * c4 + 3) * 33];
#pragma unroll
            for (int r = 0; r < 8; ++r) {
                const float4 qv = *(const float4*)&qbase[r * 128 + c4 * 4];
                acc[r] += qv.x * k0 + qv.y * k1 + qv.z * k2 + qv.w * k3;
            }
        }
#pragma unroll
        for (int r = 0; r < 8; ++r) {
            float v = acc[r];
            float mx = v;
#pragma unroll
            for (int off = 16; off; off >>= 1)
                mx = fmaxf(mx, __shfl_xor_sync(0xffffffffu, mx, off));
            float e = __expf(v - mx);
            float s = e;
#pragma unroll
            for (int off = 16; off; off >>= 1)
                s += __shfl_xor_sync(0xffffffffu, s, off);
            sc[ws * 1024 + (rb + r) * 32 + lane] = e / s;
        }
    }
    __syncthreads();

    // -------- phase 3: column sums of softmax --------
    if (tid < 128) {
        int ws = tid >> 5, m = tid & 31;
        float s = 0.f;
#pragma unroll 8
        for (int l = 0; l < 32; ++l) s += sc[ws * 1024 + l * 32 + m];
        scol[tid] = s;
    }
    __syncthreads();

    // -------- phase 4: y = scol @ X --------
    {
        int ws = tid >> 7, k = tid & 127;
        int w = ws >> 1, sel = ws & 1;
        const float* sp = &scol[ws * 32];
        const float* xb = &xTp[k * 72 + w * 36];
        float acc = 0.f;
#pragma unroll 8
        for (int m = 0; m < 32; ++m) acc += sp[m] * xb[m];
        if (sel && k < P_D) {
            const float* xd = &xTd[k * 72 + w * 36];
#pragma unroll 8
            for (int m = 0; m < 32; ++m) acc += sp[m] * xd[m];
        }
        yv[tid] = acc;
    }
    __syncthreads();

    // -------- phase 5: emb = y @ Wvl + bvl  ->  g_emb --------
    {
        int ws = tid >> 7, c = tid & 127;
        int w = ws >> 1, sel = ws & 1;
        const float* yp = &yv[ws * 128];
        float acc = g_bvl[c];
#pragma unroll 4
        for (int k = 0; k < 128; ++k) acc += yp[k] * g_Wvl[k * 128 + c];
        g_emb[((long)sel * NWALK + 2 * blk + w) * 128 + c] = acc;
    }
}

// ---------------------------------------------------------------------------
// Kernel 2: path attention. One block per (sel, batch) -> 256 blocks, 512 thr.
// ---------------------------------------------------------------------------
#define K2_EMBT  0
#define K2_Q     (128 * 68)                 // 8704
#define K2_KT    (K2_Q + 64 * 128)          // 16896
#define K2_SC    (K2_KT + 128 * 65)         // 25216
#define K2_SCOL  (K2_SC + 64 * 64)          // 29312
#define K2_YV    (K2_SCOL + 64)             // 29376
#define K2_SMEM  ((K2_YV + 128) * 4)        // 118016 bytes

__global__ void __launch_bounds__(512, 1)
path_kernel(const float* __restrict__ Wqp, const float* __restrict__ bqp,
            const float* __restrict__ Wkp, const float* __restrict__ bkp,
            const float* __restrict__ Wvp, const float* __restrict__ bvp,
            float* __restrict__ out) {
    extern __shared__ float sm[];
    float* embT = sm + K2_EMBT;   // [128][68]  (k, m)
    float* q2   = sm + K2_Q;      // [64][128]
    float* kT2  = sm + K2_KT;     // [128][65]  (c, m)
    float* sc   = sm + K2_SC;     // [64][64]
    float* scol = sm + K2_SCOL;
    float* yv   = sm + K2_YV;

    const int tid = threadIdx.x;
    const int sel = blockIdx.x >> 7;
    const int b   = blockIdx.x & 127;
    const float* emb = &g_emb[((long)sel * N_B + b) * (N_W * M_D)];

    for (int idx = tid; idx < N_W * M_D; idx += 512) {
        int m = idx >> 7, k = idx & 127;
        embT[k * 68 + m] = emb[idx];
    }
    __syncthreads();

    // projections q,k : emb @ W + b
    {
        const int c  = tid & 127;
        const int r0 = (tid >> 7) * 16;
#pragma unroll
        for (int mat = 0; mat < 2; ++mat) {
            const float* W  = mat ? Wkp : Wqp;
            const float* bb = mat ? bkp : bqp;
            float acc[16];
#pragma unroll
            for (int i = 0; i < 16; ++i) acc[i] = 0.f;
#pragma unroll 2
            for (int kk = 0; kk < 128; ++kk) {
                float wv = W[kk * 128 + c];
                const float4 e0 = *(const float4*)&embT[kk * 68 + r0];
                const float4 e1 = *(const float4*)&embT[kk * 68 + r0 + 4];
                const float4 e2 = *(const float4*)&embT[kk * 68 + r0 + 8];
                const float4 e3 = *(const float4*)&embT[kk * 68 + r0 + 12];
                acc[0]  += e0.x * wv; acc[1]  += e0.y * wv; acc[2]  += e0.z * wv; acc[3]  += e0.w * wv;
                acc[4]  += e1.x * wv; acc[5]  += e1.y * wv; acc[6]  += e1.z * wv; acc[7]  += e1.w * wv;
                acc[8]  += e2.x * wv; acc[9]  += e2.y * wv; acc[10] += e2.z * wv; acc[11] += e2.w * wv;
                acc[12] += e3.x * wv; acc[13] += e3.y * wv; acc[14] += e3.z * wv; acc[15] += e3.w * wv;
            }
            float bias = bb[c];
            if (mat == 0) {
#pragma unroll
                for (int i = 0; i < 16; ++i) q2[(r0 + i) * 128 + c] = acc[i] + bias;
            } else {
#pragma unroll
                for (int i = 0; i < 16; ++i) kT2[c * 65 + (r0 + i)] = acc[i] + bias;
            }
        }
    }
    __syncthreads();

    // scores + softmax: warp per 4 rows; lane covers m and m+32
    {
        const int lane = tid & 31;
        const int wid  = tid >> 5;
        const int lb   = wid * 4;
        const float* q0 = &q2[(lb + 0) * 128];
        const float* q1 = q0 + 128;
        const float* q3 = q0 + 384;
        const float* qq2 = q0 + 256;
        const float* kbA = &kT2[lane];
        const float* kbB = &kT2[lane + 32];
        float aA[4] = {0.f, 0.f, 0.f, 0.f};
        float aB[4] = {0.f, 0.f, 0.f, 0.f};
#pragma unroll 4
        for (int cc = 0; cc < 128; ++cc) {
            float k0 = kbA[cc * 65];
            float k1 = kbB[cc * 65];
            float v0 = q0[cc], v1 = q1[cc], v2 = qq2[cc], v3 = q3[cc];
            aA[0] += v0 * k0; aB[0] += v0 * k1;
            aA[1] += v1 * k0; aB[1] += v1 * k1;
            aA[2] += v2 * k0; aB[2] += v2 * k1;
            aA[3] += v3 * k0; aB[3] += v3 * k1;
        }
#pragma unroll
        for (int i = 0; i < 4; ++i) {
            float x0 = aA[i] * SCALE, x1 = aB[i] * SCALE;
            float mx = fmaxf(x0, x1);
#pragma unroll
            for (int off = 16; off; off >>= 1)
                mx = fmaxf(mx, __shfl_xor_sync(0xffffffffu, mx, off));
            float e0 = __expf(x0 - mx), e1 = __expf(x1 - mx);
            float s = e0 + e1;
#pragma unroll
            for (int off = 16; off; off >>= 1)
                s += __shfl_xor_sync(0xffffffffu, s, off);
            float inv = 1.f / s;
            sc[(lb + i) * 64 + lane]      = e0 * inv;
            sc[(lb + i) * 64 + lane + 32] = e1 * inv;
        }
    }
    __syncthreads();

    if (tid < 64) {
        float s = 0.f;
#pragma unroll 4
        for (int l = 0; l < 64; ++l) s += sc[l * 64 + tid];
        scol[tid] = s;
    }
    __syncthreads();

    if (tid < 128) {
        float acc = 0.f;
#pragma unroll 4
        for (int m = 0; m < 64; ++m) acc += scol[m] * embT[tid * 68 + m];
        yv[tid] = acc;
    }
    __syncthreads();

    if (tid < 128) {
        float acc = 64.0f * bvp[tid];
#pragma unroll 4
        for (int k = 0; k < 128; ++k) acc += yv[k] * Wvp[k * 128 + tid];
        out[sel * (N_B * M_D) + b * 128 + tid] = acc;
    }
}

// ---------------------------------------------------------------------------
extern "C" void kernel_launch(void* const* d_in, const int* in_sizes, int n_in,
                              void* d_out, int out_size) {
    const float* timef = (const float*)d_in[0];
    const float* posf  = (const float*)d_in[1];
    const float* negf  = (const float*)d_in[2];
    const float* wgt   = (const float*)d_in[3];
    const int*   sgn   = (const int*)  d_in[4];
    const float* Wq    = (const float*)d_in[5];
    const float* bq    = (const float*)d_in[6];
    const float* Wk    = (const float*)d_in[7];
    const float* bk    = (const float*)d_in[8];
    const float* Wv    = (const float*)d_in[9];
    const float* bv    = (const float*)d_in[10];
    const float* Wl    = (const float*)d_in[11];
    const float* bl    = (const float*)d_in[12];
    const float* Wqp   = (const float*)d_in[13];
    const float* bqp   = (const float*)d_in[14];
    const float* Wkp   = (const float*)d_in[15];
    const float* bkp   = (const float*)d_in[16];
    const float* Wvp   = (const float*)d_in[17];
    const float* bvp   = (const float*)d_in[18];

    cudaFuncSetAttribute(walk_kernel, cudaFuncAttributeMaxDynamicSharedMemorySize, K1_SMEM);
    cudaFuncSetAttribute(path_kernel, cudaFuncAttributeMaxDynamicSharedMemorySize, K2_SMEM);

    prep_kernel<<<129, 512>>>(Wv, bv, Wl, bl);
    walk_kernel<<<NWALK / 2, 512, K1_SMEM>>>(timef, posf, negf, wgt, sgn, Wq, bq, Wk, bk);
    path_kernel<<<256, 512, K2_SMEM>>>(Wqp, bqp, Wkp, bkp, Wvp, bvp, (float*)d_out);
}

// round 3
// speedup vs baseline: 1.9007x; 1.9007x over previous
#include <cuda_runtime.h>

// Problem constants
#define N_B   128
#define N_W   64
#define L_W   32
#define T_D   108
#define P_D   19
#define F_D   128
#define M_D   128
#define NWALK 8192          // N_B * N_W
#define SCALE 0.08838834764831845f   // 1/sqrt(128)

// Scratch (device globals; no allocation allowed)
__device__ float g_y[2 * NWALK * M_D];     // pre-Wvl walk vectors (8 MB)
__device__ float g_Wvl[F_D * M_D];         // Wv @ Wl folded
__device__ float g_bvl[M_D];               // 32*bv@Wl + bl

// ---------------------------------------------------------------------------
// Kernel 0: fold Wvl = Wv @ Wl ; bvl = 32*bv@Wl + bl   (split-K, 512 thr)
// ---------------------------------------------------------------------------
__global__ void prep_kernel(const float* __restrict__ Wv, const float* __restrict__ bv,
                            const float* __restrict__ Wl, const float* __restrict__ bl) {
    __shared__ float part[4][128];
    const int c = threadIdx.x & 127;
    const int s = threadIdx.x >> 7;           // 0..3 k-slice
    const int j0 = s * 32;
    float acc = 0.f;
    if (blockIdx.x < 128) {
        const int k = blockIdx.x;
#pragma unroll 8
        for (int j = 0; j < 32; ++j) acc += Wv[k * 128 + j0 + j] * Wl[(j0 + j) * 128 + c];
    } else {
#pragma unroll 8
        for (int j = 0; j < 32; ++j) acc += 32.0f * bv[j0 + j] * Wl[(j0 + j) * 128 + c];
    }
    part[s][c] = acc;
    __syncthreads();
    if (threadIdx.x < 128) {
        float r = part[0][c] + part[1][c] + part[2][c] + part[3][c];
        if (blockIdx.x < 128) g_Wvl[blockIdx.x * 128 + c] = r;
        else                  g_bvl[c] = r + bl[c];
    }
}

// ---------------------------------------------------------------------------
// Kernel 1: per-walk attention. One block per walk (8192 blocks, 512 thr, occ 2).
// Shared layout (floats):
//   xTp [128][36]  transposed pos-selected features
//   xTd [19][36]   delta (neg-selected - pos-selected), first 19 rows
//   qS  [2][32][128]  q rows, pre-scaled
//   kT  [2][128][33]  k transposed, stride 33 (conflict-free)
//   sc  [2][32][32]   softmax probs
//   scol[64]
// ---------------------------------------------------------------------------
#define K1_XTP   0
#define K1_XTD   (128 * 36)                 // 4608
#define K1_QS    (K1_XTD + P_D * 36)        // 5292
#define K1_KT    (K1_QS + 2 * 32 * 128)     // 13484
#define K1_SC    (K1_KT + 2 * 128 * 33)     // 21932
#define K1_SCOL  (K1_SC + 2 * 32 * 32)      // 23980
#define K1_SMEM  ((K1_SCOL + 64) * 4)       // 96176 bytes

__global__ void __launch_bounds__(512, 2)
walk_kernel(const float* __restrict__ timef, const float* __restrict__ posf,
            const float* __restrict__ negf, const float* __restrict__ wgt,
            const int* __restrict__ sgn,
            const float* __restrict__ Wq, const float* __restrict__ bq,
            const float* __restrict__ Wk, const float* __restrict__ bk) {
    extern __shared__ float sm[];
    float* xTp  = sm + K1_XTP;
    float* xTd  = sm + K1_XTD;
    float* qS   = sm + K1_QS;
    float* kT   = sm + K1_KT;
    float* sc   = sm + K1_SC;
    float* scol = sm + K1_SCOL;

    const int tid = threadIdx.x;
    const int w = blockIdx.x;
    const long tbase = (long)w * (L_W * T_D);
    const long pbase = (long)w * (L_W * P_D);
    const int  wbase = w * L_W;

    // -------- phase 0: load + transpose features --------
    for (int idx = tid; idx < L_W * T_D; idx += 512) {
        int r = idx / T_D, t = idx - r * T_D;
        xTp[(P_D + t) * 36 + r] = timef[tbase + idx];
    }
    if (tid < L_W) xTp[127 * 36 + tid] = wgt[wbase + tid];
    for (int idx = tid; idx < L_W * P_D; idx += 512) {
        int r = idx / P_D, p = idx - r * P_D;
        float vp = posf[pbase + idx];
        float vn = negf[pbase + idx];
        bool ps = (sgn[wbase + r] > 0);
        float xp = ps ? vp : vn;
        float xn = ps ? vn : vp;
        xTp[p * 36 + r] = xp;
        xTd[p * 36 + r] = xn - xp;
    }
    __syncthreads();

    // -------- phase 1: Q,K projections (pos full pass + 19-row delta) --------
    {
        const int c  = tid & 127;
        const int r0 = (tid >> 7) * 8;       // 0,8,16,24
#pragma unroll
        for (int mat = 0; mat < 2; ++mat) {
            const float* W  = mat ? Wk : Wq;
            const float* bb = mat ? bk : bq;
            float acc[8];
#pragma unroll
            for (int i = 0; i < 8; ++i) acc[i] = 0.f;
#pragma unroll 4
            for (int kk = 0; kk < 128; ++kk) {
                float wv = W[kk * 128 + c];
                const float4 a0 = *(const float4*)&xTp[kk * 36 + r0];
                const float4 a1 = *(const float4*)&xTp[kk * 36 + r0 + 4];
                acc[0] += a0.x * wv; acc[1] += a0.y * wv;
                acc[2] += a0.z * wv; acc[3] += a0.w * wv;
                acc[4] += a1.x * wv; acc[5] += a1.y * wv;
                acc[6] += a1.z * wv; acc[7] += a1.w * wv;
            }
            float dac[8];
#pragma unroll
            for (int i = 0; i < 8; ++i) dac[i] = 0.f;
            for (int kk = 0; kk < P_D; ++kk) {
                float wv = W[kk * 128 + c];
                const float4 a0 = *(const float4*)&xTd[kk * 36 + r0];
                const float4 a1 = *(const float4*)&xTd[kk * 36 + r0 + 4];
                dac[0] += a0.x * wv; dac[1] += a0.y * wv;
                dac[2] += a0.z * wv; dac[3] += a0.w * wv;
                dac[4] += a1.x * wv; dac[5] += a1.y * wv;
                dac[6] += a1.z * wv; dac[7] += a1.w * wv;
            }
            const float bias = bb[c];
            if (mat == 0) {
#pragma unroll
                for (int i = 0; i < 8; ++i) {
                    int row = r0 + i;
                    qS[row * 128 + c]        = (acc[i] + bias) * SCALE;
                    qS[4096 + row * 128 + c] = (acc[i] + dac[i] + bias) * SCALE;
                }
            } else {
#pragma unroll
                for (int i = 0; i < 8; ++i) {
                    int row = r0 + i;
                    kT[c * 33 + row]        = acc[i] + bias;
                    kT[4224 + c * 33 + row] = acc[i] + dac[i] + bias;
                }
            }
        }
    }
    __syncthreads();

    // -------- phase 2: scores + softmax (warp per 4 rows, float4 q) --------
    {
        const int lane = tid & 31;
        const int wid  = tid >> 5;          // 0..15
        const int sel  = wid >> 3;          // warps 0-7 -> pos, 8-15 -> neg
        const int lb   = (wid & 7) * 4;     // 4 rows per warp
        const float* qbase = &qS[sel * 4096 + lb * 128];
        const float* kb    = &kT[sel * 4224 + lane];
        float acc[4] = {0.f, 0.f, 0.f, 0.f};
#pragma unroll 4
        for (int c4 = 0; c4 < 32; ++c4) {
            float k0 = kb[(4 * c4 + 0) * 33];
            float k1 = kb[(4 * c4 + 1) * 33];
            float k2 = kb[(4 * c4 + 2) * 33];
            float k3 = kb[(4 * c4 + 3) * 33];
#pragma unroll
            for (int r = 0; r < 4; ++r) {
                const float4 qv = *(const float4*)&qbase[r * 128 + c4 * 4];
                acc[r] += qv.x * k0 + qv.y * k1 + qv.z * k2 + qv.w * k3;
            }
        }
#pragma unroll
        for (int r = 0; r < 4; ++r) {
            float v = acc[r];
            float mx = v;
#pragma unroll
            for (int off = 16; off; off >>= 1)
                mx = fmaxf(mx, __shfl_xor_sync(0xffffffffu, mx, off));
            float e = __expf(v - mx);
            float s = e;
#pragma unroll
            for (int off = 16; off; off >>= 1)
                s += __shfl_xor_sync(0xffffffffu, s, off);
            sc[sel * 1024 + (lb + r) * 32 + lane] = e / s;
        }
    }
    __syncthreads();

    // -------- phase 3: column sums of softmax --------
    if (tid < 64) {
        int sel = tid >> 5, m = tid & 31;
        float s = 0.f;
#pragma unroll 8
        for (int l = 0; l < 32; ++l) s += sc[sel * 1024 + l * 32 + m];
        scol[tid] = s;
    }
    __syncthreads();

    // -------- phase 4: y = scol @ X  ->  g_y --------
    if (tid < 256) {
        int sel = tid >> 7, k = tid & 127;
        const float* sp = &scol[sel * 32];
        const float* xb = &xTp[k * 36];
        float acc = 0.f;
#pragma unroll 8
        for (int m = 0; m < 32; ++m) acc += sp[m] * xb[m];
        if (sel && k < P_D) {
            const float* xd = &xTd[k * 36];
#pragma unroll 8
            for (int m = 0; m < 32; ++m) acc += sp[m] * xd[m];
        }
        g_y[((long)sel * NWALK + w) * 128 + k] = acc;
    }
}

// ---------------------------------------------------------------------------
// Kernel 2: emb fold + path attention. One block per (sel, batch); 512 thr.
// Shared layout (floats):
//   embT [128][68]   emb transposed (k, m)
//   WvlS [128][128]  Wvl staged
//   A: yT [128][68]  (phase A)   then  q2[64][128] kT2[128][65] sc[64][64] scol[64] yv[128]
// ---------------------------------------------------------------------------
#define K2_EMBT  0
#define K2_WVL   (128 * 68)                  // 8704
#define K2_A     (K2_WVL + 128 * 128)        // 25088
#define K2_Q     K2_A                        // q2 aliases yT
#define K2_KT    (K2_Q + 64 * 128)           // 33280
#define K2_SC    (K2_KT + 128 * 65)          // 41600
#define K2_SCOL  (K2_SC + 64 * 64)           // 45696
#define K2_YV    (K2_SCOL + 64)              // 45760
#define K2_SMEM  ((K2_YV + 128) * 4)         // 183552 bytes

__global__ void __launch_bounds__(512, 1)
path_kernel(const float* __restrict__ Wqp, const float* __restrict__ bqp,
            const float* __restrict__ Wkp, const float* __restrict__ bkp,
            const float* __restrict__ Wvp, const float* __restrict__ bvp,
            float* __restrict__ out) {
    extern __shared__ float sm[];
    float* embT = sm + K2_EMBT;
    float* WvlS = sm + K2_WVL;
    float* yT   = sm + K2_A;
    float* q2   = sm + K2_Q;
    float* kT2  = sm + K2_KT;
    float* sc   = sm + K2_SC;
    float* scol = sm + K2_SCOL;
    float* yv   = sm + K2_YV;

    const int tid = threadIdx.x;
    const int sel = blockIdx.x >> 7;
    const int b   = blockIdx.x & 127;
    const float* yg = &g_y[((long)sel * NWALK + b * N_W) * M_D];

    // -------- phase A0: stage y (transposed) + Wvl --------
    for (int idx = tid; idx < N_W * M_D; idx += 512) {
        int m = idx >> 7, j = idx & 127;
        yT[j * 68 + m] = yg[idx];
    }
    for (int idx = tid; idx < 128 * 128; idx += 512)
        WvlS[idx] = g_Wvl[idx];
    __syncthreads();

    // -------- phase A1: embT = (y @ Wvl + bvl)^T --------
    {
        const int c  = tid & 127;            // output k
        const int r0 = (tid >> 7) * 16;      // 16 m-rows
        float acc[16];
#pragma unroll
        for (int i = 0; i < 16; ++i) acc[i] = 0.f;
#pragma unroll 2
        for (int j = 0; j < 128; ++j) {
            float wv = WvlS[j * 128 + c];
            const float4 e0 = *(const float4*)&yT[j * 68 + r0];
            const float4 e1 = *(const float4*)&yT[j * 68 + r0 + 4];
            const float4 e2 = *(const float4*)&yT[j * 68 + r0 + 8];
            const float4 e3 = *(const float4*)&yT[j * 68 + r0 + 12];
            acc[0]  += e0.x * wv; acc[1]  += e0.y * wv; acc[2]  += e0.z * wv; acc[3]  += e0.w * wv;
            acc[4]  += e1.x * wv; acc[5]  += e1.y * wv; acc[6]  += e1.z * wv; acc[7]  += e1.w * wv;
            acc[8]  += e2.x * wv; acc[9]  += e2.y * wv; acc[10] += e2.z * wv; acc[11] += e2.w * wv;
            acc[12] += e3.x * wv; acc[13] += e3.y * wv; acc[14] += e3.z * wv; acc[15] += e3.w * wv;
        }
        float bias = g_bvl[c];
        __syncthreads();                      // yT dead after this point
#pragma unroll
        for (int i = 0; i < 16; ++i) embT[c * 68 + (r0 + i)] = acc[i] + bias;
    }
    __syncthreads();

    // -------- phase B: projections q,k = emb @ W + b --------
    {
        const int c  = tid & 127;
        const int r0 = (tid >> 7) * 16;
#pragma unroll
        for (int mat = 0; mat < 2; ++mat) {
            const float* W  = mat ? Wkp : Wqp;
            const float* bb = mat ? bkp : bqp;
            float acc[16];
#pragma unroll
            for (int i = 0; i < 16; ++i) acc[i] = 0.f;
#pragma unroll 2
            for (int kk = 0; kk < 128; ++kk) {
                float wv = W[kk * 128 + c];
                const float4 e0 = *(const float4*)&embT[kk * 68 + r0];
                const float4 e1 = *(const float4*)&embT[kk * 68 + r0 + 4];
                const float4 e2 = *(const float4*)&embT[kk * 68 + r0 + 8];
                const float4 e3 = *(const float4*)&embT[kk * 68 + r0 + 12];
                acc[0]  += e0.x * wv; acc[1]  += e0.y * wv; acc[2]  += e0.z * wv; acc[3]  += e0.w * wv;
                acc[4]  += e1.x * wv; acc[5]  += e1.y * wv; acc[6]  += e1.z * wv; acc[7]  += e1.w * wv;
                acc[8]  += e2.x * wv; acc[9]  += e2.y * wv; acc[10] += e2.z * wv; acc[11] += e2.w * wv;
                acc[12] += e3.x * wv; acc[13] += e3.y * wv; acc[14] += e3.z * wv; acc[15] += e3.w * wv;
            }
            float bias = bb[c];
            if (mat == 0) {
#pragma unroll
                for (int i = 0; i < 16; ++i) q2[(r0 + i) * 128 + c] = acc[i] + bias;
            } else {
#pragma unroll
                for (int i = 0; i < 16; ++i) kT2[c * 65 + (r0 + i)] = acc[i] + bias;
            }
        }
    }
    __syncthreads();

    // -------- phase C: scores + softmax --------
    {
        const int lane = tid & 31;
        const int wid  = tid >> 5;
        const int lb   = wid * 4;
        const float* q0 = &q2[(lb + 0) * 128];
        const float* q1 = q0 + 128;
        const float* qq2 = q0 + 256;
        const float* q3 = q0 + 384;
        const float* kbA = &kT2[lane];
        const float* kbB = &kT2[lane + 32];
        float aA[4] = {0.f, 0.f, 0.f, 0.f};
        float aB[4] = {0.f, 0.f, 0.f, 0.f};
#pragma unroll 4
        for (int cc = 0; cc < 128; ++cc) {
            float k0 = kbA[cc * 65];
            float k1 = kbB[cc * 65];
            float v0 = q0[cc], v1 = q1[cc], v2 = qq2[cc], v3 = q3[cc];
            aA[0] += v0 * k0; aB[0] += v0 * k1;
            aA[1] += v1 * k0; aB[1] += v1 * k1;
            aA[2] += v2 * k0; aB[2] += v2 * k1;
            aA[3] += v3 * k0; aB[3] += v3 * k1;
        }
#pragma unroll
        for (int i = 0; i < 4; ++i) {
            float x0 = aA[i] * SCALE, x1 = aB[i] * SCALE;
            float mx = fmaxf(x0, x1);
#pragma unroll
            for (int off = 16; off; off >>= 1)
                mx = fmaxf(mx, __shfl_xor_sync(0xffffffffu, mx, off));
            float e0 = __expf(x0 - mx), e1 = __expf(x1 - mx);
            float s = e0 + e1;
#pragma unroll
            for (int off = 16; off; off >>= 1)
                s += __shfl_xor_sync(0xffffffffu, s, off);
            float inv = 1.f / s;
            sc[(lb + i) * 64 + lane]      = e0 * inv;
            sc[(lb + i) * 64 + lane + 32] = e1 * inv;
        }
    }
    __syncthreads();

    if (tid < 64) {
        float s = 0.f;
#pragma unroll 4
        for (int l = 0; l < 64; ++l) s += sc[l * 64 + tid];
        scol[tid] = s;
    }
    __syncthreads();

    if (tid < 128) {
        float acc = 0.f;
#pragma unroll 4
        for (int m = 0; m < 64; ++m) acc += scol[m] * embT[tid * 68 + m];
        yv[tid] = acc;
    }
    __syncthreads();

    if (tid < 128) {
        float acc = 64.0f * bvp[tid];
#pragma unroll 4
        for (int k = 0; k < 128; ++k) acc += yv[k] * Wvp[k * 128 + tid];
        out[sel * (N_B * M_D) + b * 128 + tid] = acc;
    }
}

// Launch-count pad so ncu -s 5 lands on walk_kernel (4 launches per call).
__global__ void pad_kernel() {}

// ---------------------------------------------------------------------------
extern "C" void kernel_launch(void* const* d_in, const int* in_sizes, int n_in,
                              void* d_out, int out_size) {
    const float* timef = (const float*)d_in[0];
    const float* posf  = (const float*)d_in[1];
    const float* negf  = (const float*)d_in[2];
    const float* wgt   = (const float*)d_in[3];
    const int*   sgn   = (const int*)  d_in[4];
    const float* Wq    = (const float*)d_in[5];
    const float* bq    = (const float*)d_in[6];
    const float* Wk    = (const float*)d_in[7];
    const float* bk    = (const float*)d_in[8];
    const float* Wv    = (const float*)d_in[9];
    const float* bv    = (const float*)d_in[10];
    const float* Wl    = (const float*)d_in[11];
    const float* bl    = (const float*)d_in[12];
    const float* Wqp   = (const float*)d_in[13];
    const float* bqp   = (const float*)d_in[14];
    const float* Wkp   = (const float*)d_in[15];
    const float* bkp   = (const float*)d_in[16];
    const float* Wvp   = (const float*)d_in[17];
    const float* bvp   = (const float*)d_in[18];

    cudaFuncSetAttribute(walk_kernel, cudaFuncAttributeMaxDynamicSharedMemorySize, K1_SMEM);
    cudaFuncSetAttribute(path_kernel, cudaFuncAttributeMaxDynamicSharedMemorySize, K2_SMEM);

    prep_kernel<<<129, 512>>>(Wv, bv, Wl, bl);
    walk_kernel<<<NWALK, 512, K1_SMEM>>>(timef, posf, negf, wgt, sgn, Wq, bq, Wk, bk);
    path_kernel<<<256, 512, K2_SMEM>>>(Wqp, bqp, Wkp, bkp, Wvp, bvp, (float*)d_out);
    pad_kernel<<<1, 32>>>();
}